// round 12
// baseline (speedup 1.0000x reference)
#include <cuda_runtime.h>
#include <cstdint>

// Problem constants
constexpr int B_  = 256;
constexpr int T_  = 512;
constexpr int H_  = 256;
constexpr int MTOT = B_ * T_;
constexpr size_t MH = (size_t)MTOT * H_;

// Scan decomposition: 32 batch groups of 8 rows; 8 column CTAs per group;
// each CTA serves TWO groups (alpha, beta) -> 16 pairs x 8 = 128 CTAs.
constexpr int NC  = 8;
constexpr int HC  = 32;
constexpr int NG  = 32;   // batch groups
constexpr int GR  = 8;    // rows per group
constexpr int AST = 260;  // asm row stride (floats) - bank-conflict pad

// ---------------- device scratch ----------------
__device__ float g_xp[3 * MH];                 // projected inputs [gate][m][H]
__device__ float g_h [2][NG][GR][H_];          // pre-decayed h, double-buffered
__device__ float g_rh[2][NG][GR][H_];          // r*h_dec, double-buffered
__device__ unsigned g_cnt_rh[NG][NC][32];      // per-producer flags (128B padded)
__device__ unsigned g_cnt_h [NG][NC][32];

// ---------------- f32x2 helpers ----------------
__device__ __forceinline__ unsigned long long pack2(float a, float b) {
    unsigned long long r;
    asm("mov.b64 %0, {%1,%2};" : "=l"(r) : "f"(a), "f"(b));
    return r;
}
__device__ __forceinline__ void fma2(unsigned long long& d, unsigned long long a, unsigned long long b) {
    asm("fma.rn.f32x2 %0, %1, %2, %0;" : "+l"(d) : "l"(a), "l"(b));
}
__device__ __forceinline__ unsigned long long add2(unsigned long long a, unsigned long long b) {
    unsigned long long r;
    asm("add.rn.f32x2 %0, %1, %2;" : "=l"(r) : "l"(a), "l"(b));
    return r;
}
__device__ __forceinline__ float fold2(unsigned long long v) {
    float lo, hi;
    asm("mov.b64 {%0,%1}, %2;" : "=f"(lo), "=f"(hi) : "l"(v));
    return lo + hi;
}

__device__ __forceinline__ float sigmoid_(float v) {
    float e = __expf(-v);
    return __fdividef(1.f, 1.f + e);
}
__device__ __forceinline__ float tanh_(float v) {
    float e = __expf(2.f * v);
    return __fdividef(e - 1.f, e + 1.f);
}

// ---------------- flag primitives (K* style: tid0 release-store value) -------
__device__ __forceinline__ void set_flag(unsigned* f, unsigned v) {
    asm volatile("st.release.gpu.global.u32 [%0], %1;" :: "l"(f), "r"(v) : "memory");
}
__device__ __forceinline__ void poll_ge(const unsigned* f, unsigned need) {
    unsigned v;
    do {
        asm volatile("ld.acquire.gpu.global.u32 %0, [%1];" : "=r"(v) : "l"(f) : "memory");
    } while ((int)v < (int)need);
}

// ================= projection GEMM (proven, ~571us) =================
__global__ __launch_bounds__(256) void proj_kernel(
    const float* __restrict__ x,
    const float* __restrict__ Wz, const float* __restrict__ Wr, const float* __restrict__ Wh,
    const float* __restrict__ bz, const float* __restrict__ br, const float* __restrict__ bh)
{
    __shared__ float As[32 * 132];
    __shared__ float Bs[32 * 64];

    const int g = blockIdx.z;
    const float* W    = (g == 0) ? Wz : (g == 1) ? Wr : Wh;
    const float* bias = (g == 0) ? bz : (g == 1) ? br : bh;
    float* out = g_xp + (size_t)g * MH;

    const int mtile = blockIdx.x * 128;
    const int ntile = blockIdx.y * 64;
    const int tid = threadIdx.x;
    const int tm = tid >> 4;
    const int tn = tid & 15;

    float acc[8][4] = {};

    for (int kc = 0; kc < 128; kc += 32) {
        __syncthreads();
        #pragma unroll
        for (int it = 0; it < 4; ++it) {
            int idx = tid + it * 256;
            int m = idx >> 3, c4 = idx & 7;
            float4 v = *(const float4*)&x[(size_t)(mtile + m) * 128 + kc + c4 * 4];
            As[(c4 * 4 + 0) * 132 + m] = v.x;
            As[(c4 * 4 + 1) * 132 + m] = v.y;
            As[(c4 * 4 + 2) * 132 + m] = v.z;
            As[(c4 * 4 + 3) * 132 + m] = v.w;
        }
        #pragma unroll
        for (int it = 0; it < 2; ++it) {
            int idx = tid + it * 256;
            int kk = idx >> 4, n4 = idx & 15;
            float4 v = *(const float4*)&W[(size_t)(kc + kk) * 256 + ntile + n4 * 4];
            *(float4*)&Bs[kk * 64 + n4 * 4] = v;
        }
        __syncthreads();

        #pragma unroll
        for (int kk = 0; kk < 32; ++kk) {
            float4 a0 = *(const float4*)&As[kk * 132 + tm * 8];
            float4 a1 = *(const float4*)&As[kk * 132 + tm * 8 + 4];
            float4 bv = *(const float4*)&Bs[kk * 64 + tn * 4];
            float a[8] = {a0.x, a0.y, a0.z, a0.w, a1.x, a1.y, a1.z, a1.w};
            #pragma unroll
            for (int i = 0; i < 8; i++) {
                acc[i][0] += a[i] * bv.x;
                acc[i][1] += a[i] * bv.y;
                acc[i][2] += a[i] * bv.z;
                acc[i][3] += a[i] * bv.w;
            }
        }
    }

    float4 bb = *(const float4*)&bias[ntile + tn * 4];
    #pragma unroll
    for (int i = 0; i < 8; i++) {
        float4 o = make_float4(acc[i][0] + bb.x, acc[i][1] + bb.y,
                               acc[i][2] + bb.z, acc[i][3] + bb.w);
        *(float4*)&out[(size_t)(mtile + tm * 8 + i) * 256 + ntile + tn * 4] = o;
    }
}

// ================= reset: zero flags + g_h buffer 0 =================
__global__ void reset_kernel() {
    int i = blockIdx.x * 256 + threadIdx.x;
    if (i < NG * GR * H_) ((float*)g_h)[i] = 0.f;                 // g_h[0] = 0
    if (i < NG * NC * 32) {
        ((unsigned*)g_cnt_rh)[i] = 0;
        ((unsigned*)g_cnt_h)[i]  = 0;
    }
}

// ================= persistent recurrent scan (dual-chain interleave) =========
// CTA (pi, cg): columns [32cg,32cg+32) for groups ga=2pi (alpha), gb=2pi+1 (beta).
// Thread (w,l) finalizes output (row w, col j) of each group; warp w's k-slice
// is [32w,32w+32) and its gather source is CTA w.
__global__ __launch_bounds__(256, 1) void scan_kernel(
    const float* __restrict__ Uz, const float* __restrict__ Ur, const float* __restrict__ Uh,
    const float* __restrict__ hdecay, float* __restrict__ out)
{
    extern __shared__ float sm[];
    float* asm_ha  = sm;                   // [8][260]
    float* asm_hb  = sm + 2080;
    float* asm_rha = sm + 4160;
    float* asm_rhb = sm + 6240;
    unsigned long long* RZa = (unsigned long long*)(sm + 8320);          // [8][8][32] u64
    unsigned long long* RRa = RZa + 2048;
    unsigned long long* RZb = RZa + 4096;
    unsigned long long* RRb = RZa + 6144;

    const int tid = threadIdx.x;
    const int w = tid >> 5;              // warp -> k block + gather source CTA
    const int l = tid & 31;
    const int pi = blockIdx.x >> 3;      // pair index 0..15
    const int cg = blockIdx.x & 7;
    const int ga = 2 * pi, gb = 2 * pi + 1;
    const int j = cg * HC + l;
    const int b0a = ga * GR, b0b = gb * GR;

    // weights: packed f32x2 over k-pairs (shared by both groups)
    unsigned long long uz2[16], ur2[16], uh2[16];
    #pragma unroll
    for (int p = 0; p < 16; ++p) {
        int k = w * 32 + 2 * p;
        uz2[p] = pack2(Uz[(size_t)k * H_ + j], Uz[(size_t)(k + 1) * H_ + j]);
        ur2[p] = pack2(Ur[(size_t)k * H_ + j], Ur[(size_t)(k + 1) * H_ + j]);
        uh2[p] = pack2(Uh[(size_t)k * H_ + j], Uh[(size_t)(k + 1) * H_ + j]);
    }

    // flags (poll source CTA w; publish own cg)
    const unsigned* f_ha  = &g_cnt_h [ga][w][0];
    const unsigned* f_hb  = &g_cnt_h [gb][w][0];
    const unsigned* f_rha = &g_cnt_rh[ga][w][0];
    const unsigned* f_rhb = &g_cnt_rh[gb][w][0];
    unsigned* my_ha  = &g_cnt_h [ga][cg][0];
    unsigned* my_hb  = &g_cnt_h [gb][cg][0];
    unsigned* my_rha = &g_cnt_rh[ga][cg][0];
    unsigned* my_rhb = &g_cnt_rh[gb][cg][0];

    // gather mapping: lane l -> row l>>2, two float4 blocks at (l&3)*2
    const int grow = l >> 2;
    const int gblk = (l & 3) * 2;

    // x projections for t=0
    size_t ma = (size_t)(b0a + w) * T_;     // row index base (m = b*T + t)
    size_t mb = (size_t)(b0b + w) * T_;
    float xza = g_xp[ma * 256 + j],          xzb = g_xp[mb * 256 + j];
    float xra = g_xp[MH + ma * 256 + j],     xrb = g_xp[MH + mb * 256 + j];
    float xha = g_xp[2 * MH + ma * 256 + j], xhb = g_xp[2 * MH + mb * 256 + j];

    for (int t = 0; t < T_; ++t) {
        const int p  = t & 1;
        const int pn = (t + 1) & 1;
        const size_t m0 = ma + t;          // (b0a+w)*T + t
        const size_t m1 = mb + t;
        const bool more = (t + 1 < T_);

        float decA = 0.f, decB = 0.f;
        if (more) { decA = hdecay[m0 + 1]; decB = hdecay[m1 + 1]; }

        // ======== bracket Z_alpha ========
        poll_ge(f_ha, (unsigned)t);
        {
            const float4* src = (const float4*)&g_h[p][ga][grow][w * 32] + gblk;
            float4 v0 = __ldcg(src), v1 = __ldcg(src + 1);
            float4* dst = (float4*)&asm_ha[grow * AST + w * 32] + gblk;
            dst[0] = v0; dst[1] = v1;
        }
        __syncwarp();
        #pragma unroll 1
        for (int b = 0; b < GR; ++b) {
            unsigned long long az0 = 0, az1 = 0, ar0 = 0, ar1 = 0;
            const float* hrow = &asm_ha[b * AST + w * 32];
            #pragma unroll
            for (int q = 0; q < 8; ++q) {
                ulonglong2 hv = *(const ulonglong2*)(hrow + q * 4);
                fma2(az0, hv.x, uz2[2 * q]);
                fma2(az1, hv.y, uz2[2 * q + 1]);
                fma2(ar0, hv.x, ur2[2 * q]);
                fma2(ar1, hv.y, ur2[2 * q + 1]);
            }
            RZa[(w * 8 + b) * 32 + l] = add2(az0, az1);
            RRa[(w * 8 + b) * 32 + l] = add2(ar0, ar1);
        }
        __syncthreads();                       // S1
        if (tid == 0) set_flag(my_hb, (unsigned)t);   // h_beta(t) (published last iter)

        // reduce r_alpha + publish rh_alpha
        float hdA = asm_ha[w * AST + j];
        {
            unsigned long long s = 0;
            #pragma unroll
            for (int ww = 0; ww < 8; ++ww) s = add2(s, RRa[(ww * 8 + w) * 32 + l]);
            float rA = sigmoid_(fold2(s) + xra);
            __stcg(&g_rh[p][ga][w][j], rA * hdA);
        }

        // ======== bracket Z_beta ========
        poll_ge(f_hb, (unsigned)t);
        {
            const float4* src = (const float4*)&g_h[p][gb][grow][w * 32] + gblk;
            float4 v0 = __ldcg(src), v1 = __ldcg(src + 1);
            float4* dst = (float4*)&asm_hb[grow * AST + w * 32] + gblk;
            dst[0] = v0; dst[1] = v1;
        }
        __syncwarp();
        #pragma unroll 1
        for (int b = 0; b < GR; ++b) {
            unsigned long long az0 = 0, az1 = 0, ar0 = 0, ar1 = 0;
            const float* hrow = &asm_hb[b * AST + w * 32];
            #pragma unroll
            for (int q = 0; q < 8; ++q) {
                ulonglong2 hv = *(const ulonglong2*)(hrow + q * 4);
                fma2(az0, hv.x, uz2[2 * q]);
                fma2(az1, hv.y, uz2[2 * q + 1]);
                fma2(ar0, hv.x, ur2[2 * q]);
                fma2(ar1, hv.y, ur2[2 * q + 1]);
            }
            RZb[(w * 8 + b) * 32 + l] = add2(az0, az1);
            RRb[(w * 8 + b) * 32 + l] = add2(ar0, ar1);
        }
        __syncthreads();                       // S2
        if (tid == 0) set_flag(my_rha, (unsigned)(t + 1));

        // reduce r_beta + publish rh_beta; reduce z_alpha
        float hdB = asm_hb[w * AST + j];
        {
            unsigned long long s = 0;
            #pragma unroll
            for (int ww = 0; ww < 8; ++ww) s = add2(s, RRb[(ww * 8 + w) * 32 + l]);
            float rB = sigmoid_(fold2(s) + xrb);
            __stcg(&g_rh[p][gb][w][j], rB * hdB);
        }
        float zvA;
        {
            unsigned long long s = 0;
            #pragma unroll
            for (int ww = 0; ww < 8; ++ww) s = add2(s, RZa[(ww * 8 + w) * 32 + l]);
            zvA = sigmoid_(fold2(s) + xza);
        }

        // ======== bracket H_alpha ========
        poll_ge(f_rha, (unsigned)(t + 1));
        {
            const float4* src = (const float4*)&g_rh[p][ga][grow][w * 32] + gblk;
            float4 v0 = __ldcg(src), v1 = __ldcg(src + 1);
            float4* dst = (float4*)&asm_rha[grow * AST + w * 32] + gblk;
            dst[0] = v0; dst[1] = v1;
        }
        __syncwarp();
        #pragma unroll 1
        for (int b = 0; b < GR; ++b) {
            unsigned long long ah0 = 0, ah1 = 0;
            const float* hrow = &asm_rha[b * AST + w * 32];
            #pragma unroll
            for (int q = 0; q < 8; ++q) {
                ulonglong2 hv = *(const ulonglong2*)(hrow + q * 4);
                fma2(ah0, hv.x, uh2[2 * q]);
                fma2(ah1, hv.y, uh2[2 * q + 1]);
            }
            RRa[(w * 8 + b) * 32 + l] = add2(ah0, ah1);   // reuse (last read pre-S2)
        }
        __syncthreads();                       // S3
        if (tid == 0) set_flag(my_rhb, (unsigned)(t + 1));

        // h_alpha reduce + combine + publish; reduce z_beta
        {
            unsigned long long s = 0;
            #pragma unroll
            for (int ww = 0; ww < 8; ++ww) s = add2(s, RRa[(ww * 8 + w) * 32 + l]);
            float hpA = tanh_(fold2(s) + xha);
            float hA = (1.f - zvA) * hdA + zvA * hpA;
            if (more) __stcg(&g_h[pn][ga][w][j], hA * decA);
            out[m0 * 256 + j] = hA;
        }
        float zvB;
        {
            unsigned long long s = 0;
            #pragma unroll
            for (int ww = 0; ww < 8; ++ww) s = add2(s, RZb[(ww * 8 + w) * 32 + l]);
            zvB = sigmoid_(fold2(s) + xzb);
        }

        // ======== bracket H_beta ========
        poll_ge(f_rhb, (unsigned)(t + 1));
        {
            const float4* src = (const float4*)&g_rh[p][gb][grow][w * 32] + gblk;
            float4 v0 = __ldcg(src), v1 = __ldcg(src + 1);
            float4* dst = (float4*)&asm_rhb[grow * AST + w * 32] + gblk;
            dst[0] = v0; dst[1] = v1;
        }
        __syncwarp();
        #pragma unroll 1
        for (int b = 0; b < GR; ++b) {
            unsigned long long ah0 = 0, ah1 = 0;
            const float* hrow = &asm_rhb[b * AST + w * 32];
            #pragma unroll
            for (int q = 0; q < 8; ++q) {
                ulonglong2 hv = *(const ulonglong2*)(hrow + q * 4);
                fma2(ah0, hv.x, uh2[2 * q]);
                fma2(ah1, hv.y, uh2[2 * q + 1]);
            }
            RRb[(w * 8 + b) * 32 + l] = add2(ah0, ah1);   // reuse (last read pre-S3)
        }
        __syncthreads();                       // S4
        if (tid == 0) set_flag(my_ha, (unsigned)(t + 1));

        // h_beta reduce + combine + publish; x prefetch for t+1
        {
            unsigned long long s = 0;
            #pragma unroll
            for (int ww = 0; ww < 8; ++ww) s = add2(s, RRb[(ww * 8 + w) * 32 + l]);
            float hpB = tanh_(fold2(s) + xhb);
            float hB = (1.f - zvB) * hdB + zvB * hpB;
            if (more) __stcg(&g_h[pn][gb][w][j], hB * decB);
            out[m1 * 256 + j] = hB;
        }
        if (more) {
            xza = g_xp[(m0 + 1) * 256 + j];          xzb = g_xp[(m1 + 1) * 256 + j];
            xra = g_xp[MH + (m0 + 1) * 256 + j];     xrb = g_xp[MH + (m1 + 1) * 256 + j];
            xha = g_xp[2 * MH + (m0 + 1) * 256 + j]; xhb = g_xp[2 * MH + (m1 + 1) * 256 + j];
        }
    }
}

// ================= launch =================
extern "C" void kernel_launch(void* const* d_in, const int* /*in_sizes*/, int /*n_in*/,
                              void* d_out, int /*out_size*/)
{
    const float* x      = (const float*)d_in[0];
    const float* hdecay = (const float*)d_in[1];
    const float* Wr = (const float*)d_in[2];
    const float* Wz = (const float*)d_in[3];
    const float* Wh = (const float*)d_in[4];
    const float* Ur = (const float*)d_in[5];
    const float* Uz = (const float*)d_in[6];
    const float* Uh = (const float*)d_in[7];
    const float* br = (const float*)d_in[8];
    const float* bz = (const float*)d_in[9];
    const float* bh = (const float*)d_in[10];
    float* out = (float*)d_out;

    // smem: 4 asm arrays (8*260 floats) + 4 reduce arrays (2048 u64)
    constexpr int SMEM_SCAN = (8320 * 4) + (8192 * 8);   // 33280 + 65536 = 98816 B
    cudaFuncSetAttribute(scan_kernel, cudaFuncAttributeMaxDynamicSharedMemorySize, SMEM_SCAN);

    proj_kernel<<<dim3(MTOT / 128, H_ / 64, 3), 256>>>(x, Wz, Wr, Wh, bz, br, bh);
    reset_kernel<<<256, 256>>>();
    scan_kernel<<<16 * NC, 256, SMEM_SCAN>>>(Uz, Ur, Uh, hdecay, out);
}